// round 14
// baseline (speedup 1.0000x reference)
#include <cuda_runtime.h>
#include <cuda_bf16.h>

// y = x @ (A@B)^T + bias  ==  T = x@B^T (32x64);  y = T@A^T + bias
// Fused persistent kernel: 128 blocks x 256 threads.
// - XOR-swizzled conflict-free smem tiles, 2r x 4b blocking, f32x2 FMA
// - single-wave red.global.add.v2.f32 into g_T (proven best reduction)
// - ZERO-AT-END: g_T is re-zeroed after phase 2 consumes it, so each launch
//   starts with T zeroed (device globals zero-init at load; kernel boundary
//   orders the stores). Barrier #1 is GONE; REDs fire straight out of
//   phase 1. Barrier #3 (safe-to-zero) overlaps phase-2 compute.

#define BATCH 32
#define IN_F  8192
#define OUT_F 8192
#define RANK  64
#define GRID  128
#define TPB   256
#define S1_CHUNK 64
#define OTILE    64

__device__ float        g_T[BATCH * RANK];   // starts zeroed; kept zeroed
__device__ unsigned int g_bar;               // monotonic ticket counter

#define FMA2(acc, a, b) \
    asm("fma.rn.f32x2 %0, %1, %2, %0;" : "+l"(acc) : "l"(a), "l"(b))
#define ADD2(d, a, b) \
    asm("add.rn.f32x2 %0, %1, %2;" : "=l"(d) : "l"(a), "l"(b))

__device__ __forceinline__ float hsum2(unsigned long long v) {
    float lo, hi;
    asm("mov.b64 {%0, %1}, %2;" : "=f"(lo), "=f"(hi) : "l"(v));
    return lo + hi;
}

__device__ __forceinline__ unsigned bar_arrive() {
    unsigned ticket;
    asm volatile("atom.release.gpu.global.add.u32 %0, [%1], %2;"
                 : "=r"(ticket) : "l"(&g_bar), "r"(1u) : "memory");
    return (ticket / GRID + 1u) * GRID;
}

__device__ __forceinline__ void bar_wait(unsigned target) {
    #pragma unroll 1
    for (int i = 0;; i++) {
        unsigned v;
        asm volatile("ld.acquire.gpu.global.u32 %0, [%1];"
                     : "=r"(v) : "l"(&g_bar) : "memory");
        if (v >= target) break;
        if (i >= 8) __nanosleep(16);
    }
}

// swizzled float4-column (64-float row stride, no padding)
__device__ __forceinline__ int swz(int r, int c) { return c ^ ((r >> 1) & 7); }

__global__ __launch_bounds__(TPB, 1)
void lowrank_fused_kernel(const float* __restrict__ x,
                          const float* __restrict__ A,
                          const float* __restrict__ Bm,
                          const float* __restrict__ bias,
                          float* __restrict__ y) {
    __shared__ __align__(16) float A_s[OTILE * 64];      // swizzled
    __shared__ float bias_s[OTILE];
    __shared__ __align__(16) union SU {
        struct {
            float x_s[BATCH * 64];                       // plain
            float B_s[RANK * 64];                        // swizzled
        } p1;
        float T_s[BATCH * 64];                           // plain
    } u;

    const int tid = threadIdx.x;
    const int blk = blockIdx.x;
    const int k0  = blk * S1_CHUNK;
    const int o0  = blk * OTILE;

    // ---- Tile loads (256 threads) ----
    #pragma unroll
    for (int i = 0; i < 2; i++) {   // x[32][64] : 512 float4, plain
        int idx = tid + i * TPB;
        int b = idx >> 4, c = idx & 15;
        float4 v = reinterpret_cast<const float4*>(x + b * IN_F + k0)[c];
        *reinterpret_cast<float4*>(&u.p1.x_s[b * 64 + c * 4]) = v;
    }
    #pragma unroll
    for (int i = 0; i < 4; i++) {   // B[64][64] : 1024 float4, swizzled
        int idx = tid + i * TPB;
        int r = idx >> 4, c = idx & 15;
        float4 v = reinterpret_cast<const float4*>(Bm + r * IN_F + k0)[c];
        *reinterpret_cast<float4*>(&u.p1.B_s[r * 64 + swz(r, c) * 4]) = v;
    }
    #pragma unroll
    for (int i = 0; i < 4; i++) {   // A tile [64][64] : swizzled (phase 2)
        int idx = tid + i * TPB;
        int r = idx >> 4, c = idx & 15;
        float4 v = reinterpret_cast<const float4*>(A + (o0 + r) * RANK)[c];
        *reinterpret_cast<float4*>(&A_s[r * 64 + swz(r, c) * 4]) = v;
    }
    if (tid < OTILE) bias_s[tid] = bias[o0 + tid];
    __syncthreads();

    // ---- Phase 1: thread owns r-pair (2rr,2rr+1) x b-quad (4bq..4bq+3) ----
    const int rr = tid & 31;        // lane id -> conflict-free B reads
    const int bq = tid >> 5;        // warp id -> x reads broadcast
    const int b0 = bq * 4;

    unsigned long long accA[4][2], accB[4][2];
    #pragma unroll
    for (int j = 0; j < 4; j++)
        #pragma unroll
        for (int i = 0; i < 2; i++) { accA[j][i] = 0ull; accB[j][i] = 0ull; }

    #pragma unroll
    for (int k4 = 0; k4 < 16; k4++) {
        const int bc = swz(2 * rr, k4) * 4;
        ulonglong2 bv0 = *reinterpret_cast<const ulonglong2*>(&u.p1.B_s[(2 * rr)     * 64 + bc]);
        ulonglong2 bv1 = *reinterpret_cast<const ulonglong2*>(&u.p1.B_s[(2 * rr + 1) * 64 + bc]);
        #pragma unroll
        for (int j = 0; j < 4; j++) {
            ulonglong2 xv = *reinterpret_cast<const ulonglong2*>(&u.p1.x_s[(b0 + j) * 64 + k4 * 4]);
            FMA2(accA[j][0], xv.x, bv0.x);
            FMA2(accB[j][0], xv.y, bv0.y);
            FMA2(accA[j][1], xv.x, bv1.x);
            FMA2(accB[j][1], xv.y, bv1.y);
        }
    }

    // REDs fire immediately (g_T is pre-zeroed by construction).
    #pragma unroll
    for (int j = 0; j < 4; j++) {
        unsigned long long s0, s1;
        ADD2(s0, accA[j][0], accB[j][0]);
        ADD2(s1, accA[j][1], accB[j][1]);
        float f0 = hsum2(s0), f1 = hsum2(s1);
        asm volatile("red.global.add.v2.f32 [%0], {%1, %2};"
                     :: "l"(&g_T[(b0 + j) * RANK + 2 * rr]),
                        "f"(f0), "f"(f1) : "memory");
    }

    // Barrier #2: all REDs drained -> T final.
    __syncthreads();
    if (tid == 0) bar_wait(bar_arrive());
    __syncthreads();

    // ---- Phase 2: T -> smem (plain) ----
    #pragma unroll
    for (int i = 0; i < 2; i++) {
        int idx = tid + i * TPB;
        int b = idx >> 4, c = idx & 15;
        float4 v = __ldcg(reinterpret_cast<const float4*>(g_T + b * RANK) + c);
        *reinterpret_cast<float4*>(&u.T_s[b * 64 + c * 4]) = v;
    }
    __syncthreads();              // this block has fully read g_T

    // Barrier #3 ARRIVE (early): signals "done reading g_T".
    unsigned bar3_target = 0;
    if (tid == 0) bar3_target = bar_arrive();

    // ---- Phase-2 compute: y = T @ A^T + bias ----
    const int oo = rr;
    unsigned long long cA[4][2], cB[4][2];
    #pragma unroll
    for (int j = 0; j < 4; j++)
        #pragma unroll
        for (int i = 0; i < 2; i++) { cA[j][i] = 0ull; cB[j][i] = 0ull; }

    #pragma unroll
    for (int r4 = 0; r4 < 16; r4++) {
        const int ac = swz(2 * oo, r4) * 4;
        ulonglong2 av0 = *reinterpret_cast<const ulonglong2*>(&A_s[(2 * oo)     * 64 + ac]);
        ulonglong2 av1 = *reinterpret_cast<const ulonglong2*>(&A_s[(2 * oo + 1) * 64 + ac]);
        #pragma unroll
        for (int j = 0; j < 4; j++) {
            ulonglong2 tv = *reinterpret_cast<const ulonglong2*>(&u.T_s[(b0 + j) * 64 + r4 * 4]);
            FMA2(cA[j][0], tv.x, av0.x);
            FMA2(cB[j][0], tv.y, av0.y);
            FMA2(cA[j][1], tv.x, av1.x);
            FMA2(cB[j][1], tv.y, av1.y);
        }
    }

    const float2 bv2 = *reinterpret_cast<const float2*>(&bias_s[2 * oo]);
    #pragma unroll
    for (int j = 0; j < 4; j++) {
        unsigned long long s0, s1;
        ADD2(s0, cA[j][0], cB[j][0]);
        ADD2(s1, cA[j][1], cB[j][1]);
        float2 out;
        out.x = hsum2(s0) + bv2.x;
        out.y = hsum2(s1) + bv2.y;
        *reinterpret_cast<float2*>(&y[(b0 + j) * OUT_F + o0 + 2 * oo]) = out;
    }

    // Barrier #3 WAIT (late, overlapped by the compute above), then re-zero
    // this block's slice of g_T for the next launch.
    __syncthreads();
    if (tid == 0) bar_wait(bar3_target);
    __syncthreads();
    if (tid < 16) g_T[blk * 16 + tid] = 0.0f;
}

extern "C" void kernel_launch(void* const* d_in, const int* in_sizes, int n_in,
                              void* d_out, int out_size) {
    const float* x    = (const float*)d_in[0];   // [32, 8192]
    const float* A    = (const float*)d_in[1];   // [8192, 64]
    const float* Bm   = (const float*)d_in[2];   // [64, 8192]
    const float* bias = (const float*)d_in[3];   // [8192]
    float* y = (float*)d_out;                    // [32, 8192]

    lowrank_fused_kernel<<<GRID, TPB>>>(x, A, Bm, bias, y);
}